// round 5
// baseline (speedup 1.0000x reference)
#include <cuda_runtime.h>
#include <stdint.h>

// ---------------- problem constants ----------------
#define NB   64
#define CH   256
#define HH   28
#define WW   28
#define HPX  900              // 30*30 padded pixels per image
#define NPIX (NB*HPX)         // 57600
#define NPIX_PAD 57728        // slack for tap offsets on garbage rows
#define MT   128              // pixels (M) per CTA
#define NMT  (NPIX/MT)        // 450
#define NSTAGE 18             // 9 taps * 2 ic-halves (128 ic each)
#define NBUF 4
#define STAGE_BYTES 32768     // A 16KB + B 16KB
#define B_OFF 16384
#define SMEM_TOTAL (NBUF*STAGE_BYTES)   // 131072

// ---------------- device scratch (no cudaMalloc allowed) ----------------
__device__ __align__(16) int8_t  g_xs [(size_t)NPIX_PAD*CH];  // (x - z_x), pad 0
__device__ __align__(16) uint8_t g_mid[(size_t)NPIX_PAD*CH];  // conv1 out u8, pad = z_c1
__device__ __align__(16) int8_t  g_wq1[9*CH*CH];              // [tap][oc][ic]
__device__ __align__(16) int8_t  g_wq2[9*CH*CH];
__device__ int g_wsum2[CH];

// ---------------- PTX helpers ----------------
__device__ __forceinline__ uint32_t smem_u32(const void* p) {
    uint32_t a;
    asm("{ .reg .u64 t; cvta.to.shared.u64 t, %1; cvt.u32.u64 %0, t; }" : "=r"(a) : "l"(p));
    return a;
}
__device__ __forceinline__ void cp16(uint32_t sdst, const void* gsrc) {
    asm volatile("cp.async.cg.shared.global [%0], [%1], 16;" :: "r"(sdst), "l"(gsrc));
}
#define CP_COMMIT() asm volatile("cp.async.commit_group;" ::: "memory")
template <int N> __device__ __forceinline__ void cp_wait() {
    asm volatile("cp.async.wait_group %0;" :: "n"(N) : "memory");
}
__device__ __forceinline__ void ldm4(uint32_t* r, uint32_t addr) {
    asm volatile("ldmatrix.sync.aligned.m8n8.x4.shared.b16 {%0,%1,%2,%3}, [%4];"
        : "=r"(r[0]), "=r"(r[1]), "=r"(r[2]), "=r"(r[3]) : "r"(addr));
}
template <int MODE>
__device__ __forceinline__ void mma8(int* d, const uint32_t* a, const uint32_t* b) {
    if (MODE == 0)
        asm volatile("mma.sync.aligned.m16n8k32.row.col.s32.s8.s8.s32 "
            "{%0,%1,%2,%3},{%4,%5,%6,%7},{%8,%9},{%0,%1,%2,%3};"
            : "+r"(d[0]), "+r"(d[1]), "+r"(d[2]), "+r"(d[3])
            : "r"(a[0]), "r"(a[1]), "r"(a[2]), "r"(a[3]), "r"(b[0]), "r"(b[1]));
    else
        asm volatile("mma.sync.aligned.m16n8k32.row.col.s32.u8.s8.s32 "
            "{%0,%1,%2,%3},{%4,%5,%6,%7},{%8,%9},{%0,%1,%2,%3};"
            : "+r"(d[0]), "+r"(d[1]), "+r"(d[2]), "+r"(d[3])
            : "r"(a[0]), "r"(a[1]), "r"(a[2]), "r"(a[3]), "r"(b[0]), "r"(b[1]));
}

// ---------------- packing kernels ----------------
__global__ void k_init(const float* __restrict__ pz1) {
    unsigned i = blockIdx.x * blockDim.x + threadIdx.x;   // int4 slots
    unsigned per = (unsigned)((size_t)NPIX_PAD * CH / 16);  // 923648
    if (i >= per) return;
    uint32_t z  = (uint32_t)(int)rintf(*pz1) & 0xFFu;
    uint32_t zp = z * 0x01010101u;
    ((int4*)g_xs)[i]  = make_int4(0, 0, 0, 0);
    ((int4*)g_mid)[i] = make_int4((int)zp, (int)zp, (int)zp, (int)zp);
}

__global__ void k_pack_x(const float* __restrict__ x, const float* __restrict__ pzx) {
    int idx = blockIdx.x * blockDim.x + threadIdx.x;   // NB*HH*WW*CH threads
    float zx = *pzx;
    int c  = idx & 255;
    int t  = idx >> 8;
    int ow = t % WW; t /= WW;
    int oh = t % HH;
    int n  = t / HH;
    float g = x[((n*CH + c)*HH + oh)*WW + ow];
    int v = (int)rintf(__fsub_rn(g, zx));
    g_xs[((size_t)n*HPX + (oh + 1)*30 + ow + 1)*CH + c] = (int8_t)v;
}

__global__ void k_pack_w(const float* __restrict__ w, int which) {
    int idx = blockIdx.x * blockDim.x + threadIdx.x;   // 9*256*256 threads
    int ic  = idx & 255;
    int oc  = (idx >> 8) & 255;
    int tap = idx >> 16;
    int8_t v = (int8_t)(int)rintf(w[((size_t)oc*CH + ic)*9 + tap]);
    if (which == 0) g_wq1[idx] = v; else g_wq2[idx] = v;
}

__global__ void k_wsum(const float* __restrict__ w2) {
    __shared__ int red[256];
    int o = blockIdx.x;
    int s = 0;
    for (int j = threadIdx.x; j < 2304; j += 256)
        s += (int)rintf(w2[(size_t)o*2304 + j]);
    red[threadIdx.x] = s;
    __syncthreads();
    for (int d = 128; d > 0; d >>= 1) {
        if (threadIdx.x < d) red[threadIdx.x] += red[threadIdx.x + d];
        __syncthreads();
    }
    if (threadIdx.x == 0) g_wsum2[o] = red[0];
}

// ---------------- IMMA implicit-GEMM conv ----------------
// MODE 0: conv1 (s8 x s8, zero pad), writes g_mid u8
// MODE 1: conv2 (u8 x s8, z1-pad + wsum corr) + fused residual qadd -> out fp32
template <int MODE>
__global__ __launch_bounds__(256, 1) void k_conv(
    const float* __restrict__ ps_in,  const float* __restrict__ ps_w,
    const float* __restrict__ ps_out, const float* __restrict__ pz_out,
    const float* __restrict__ pz_in,
    const float* __restrict__ ps_x,  const float* __restrict__ ps_add,
    const float* __restrict__ pz_add,
    float* __restrict__ out)
{
    extern __shared__ char smem[];
    const uint32_t sb = smem_u32(smem);
    const uint8_t* act = (MODE == 0) ? (const uint8_t*)g_xs : g_mid;
    const int8_t*  wq  = (MODE == 0) ? g_wq1 : g_wq2;

    const int tid  = threadIdx.x;
    const int lane = tid & 31;
    const int wid  = tid >> 5;
    const int wm   = wid & 3;        // 4 m-warps (32 px each)
    const int wn   = wid >> 2;       // 2 n-warps (64 oc each)
    const int P0   = blockIdx.x * MT;
    const int ocb  = blockIdx.y * 128;

    int acc[2][8][4];
#pragma unroll
    for (int mt = 0; mt < 2; mt++)
#pragma unroll
        for (int nt = 0; nt < 8; nt++)
#pragma unroll
            for (int j = 0; j < 4; j++) acc[mt][nt][j] = 0;

    // stage loader: tap = s/2, ic0 = (s&1)*128; A 16KB + B 16KB, 8 cp16/thread
    auto load_stage = [&](int s) {
        int tap = s >> 1;
        int ic0 = (s & 1) << 7;
        int off = (tap / 3) * 30 + (tap % 3);
        uint32_t bufA = sb + (s % NBUF) * STAGE_BYTES;
        uint32_t bufB = bufA + B_OFF;
        const char* ga = (const char*)act + (size_t)(P0 + off) * 256 + ic0;
        const char* gb = (const char*)wq + ((size_t)tap * 256 + ocb) * 256 + ic0;
#pragma unroll
        for (int i = 0; i < 4; i++) {
            int idx = tid + i * 256;           // 0..1023
            int row = idx >> 3, c16 = idx & 7;
            uint32_t sw = (uint32_t)((c16 ^ (row & 7)) << 4) + row * 128;
            cp16(bufA + sw, ga + (size_t)row * 256 + c16 * 16);
            cp16(bufB + sw, gb + (size_t)row * 256 + c16 * 16);
        }
        CP_COMMIT();
    };

    load_stage(0); load_stage(1); load_stage(2);

    // per-lane ldmatrix row/col selectors
    const int sub  = lane >> 3;
    const int cSel = sub >> 1;
    const int rA   = wm * 32 + (lane & 7) + ((sub & 1) << 3);
    const int rB   = wn * 64 + (lane & 7) + ((sub & 1) << 3);
    const int xA   = rA & 7;
    const int xB   = rB & 7;

#pragma unroll 1
    for (int s = 0; s < NSTAGE; s++) {
        if (s < NSTAGE - 2)      cp_wait<2>();
        else if (s == NSTAGE-2)  cp_wait<1>();
        else                     cp_wait<0>();
        __syncthreads();

        uint32_t bufA = sb + (s % NBUF) * STAGE_BYTES;
        uint32_t bufB = bufA + B_OFF;
#pragma unroll
        for (int g = 0; g < 4; g++) {           // 4 k32 groups per 128B row
            const int c = (g << 1) | cSel;
            uint32_t a0[4], a1[4];
            ldm4(a0, bufA + rA * 128        + ((c ^ xA) << 4));
            ldm4(a1, bufA + (rA + 16) * 128 + ((c ^ xA) << 4));
            uint32_t bf[8][2];
#pragma unroll
            for (int nt2 = 0; nt2 < 4; nt2++) {
                uint32_t r[4];
                ldm4(r, bufB + (rB + 16 * nt2) * 128 + ((c ^ xB) << 4));
                bf[nt2*2][0]   = r[0]; bf[nt2*2][1]   = r[2];
                bf[nt2*2+1][0] = r[1]; bf[nt2*2+1][1] = r[3];
            }
#pragma unroll
            for (int nt = 0; nt < 8; nt++) {
                mma8<MODE>(acc[0][nt], a0, bf[nt]);
                mma8<MODE>(acc[1][nt], a1, bf[nt]);
            }
        }
        if (s + 3 < NSTAGE) load_stage(s + 3);
    }

    // ---------------- epilogue ----------------
    const float M  = __fdiv_rn(__fmul_rn(*ps_in, *ps_w), *ps_out);
    const float zo = *pz_out;
    const int qrow = lane >> 2;
    const int cc   = (lane & 3) << 1;
    const int ocw  = ocb + wn * 64;

    float ra = 0.f, rb = 0.f, za = 0.f;
    int z1i = 0;
    int ws[8][2];
    if (MODE == 1) {
        ra  = __fdiv_rn(*ps_x,  *ps_add);
        rb  = __fdiv_rn(*ps_out, *ps_add);
        za  = *pz_add;
        z1i = (int)rintf(*pz_in);
#pragma unroll
        for (int nt = 0; nt < 8; nt++) {
            ws[nt][0] = g_wsum2[ocw + nt*8 + cc];
            ws[nt][1] = g_wsum2[ocw + nt*8 + cc + 1];
        }
    }

#pragma unroll
    for (int mt = 0; mt < 2; mt++) {
#pragma unroll
        for (int h = 0; h < 2; h++) {
            int r  = wm*32 + mt*16 + qrow + h*8;
            int P  = P0 + r;
            int n  = P / HPX;
            int q  = P - n * HPX;
            int oh = q / 30, ow = q - oh * 30;
            if (oh >= 28 || ow >= 28) continue;

            if (MODE == 0) {
                size_t base = (size_t)(P + 31) * 256 + ocw + cc;
#pragma unroll
                for (int nt = 0; nt < 8; nt++) {
                    float v0 = rintf(__fmul_rn(M, (float)acc[mt][nt][h*2]))   + zo;
                    float v1 = rintf(__fmul_rn(M, (float)acc[mt][nt][h*2+1])) + zo;
                    v0 = fminf(fmaxf(v0, 0.f), 255.f);
                    v1 = fminf(fmaxf(v1, 0.f), 255.f);
                    uchar2 u; u.x = (uint8_t)v0; u.y = (uint8_t)v1;
                    *(uchar2*)(g_mid + base + nt*8) = u;
                }
            } else {
                size_t xbase = (size_t)(P + 31) * 256 + ocw + cc;
#pragma unroll
                for (int nt = 0; nt < 8; nt++) {
                    int a0 = acc[mt][nt][h*2]   - z1i * ws[nt][0];
                    int a1 = acc[mt][nt][h*2+1] - z1i * ws[nt][1];
                    float v0 = rintf(__fmul_rn(M, (float)a0)) + zo;
                    float v1 = rintf(__fmul_rn(M, (float)a1)) + zo;
                    v0 = fminf(fmaxf(v0, 0.f), 255.f);
                    v1 = fminf(fmaxf(v1, 0.f), 255.f);
                    float xv0 = (float)(int)g_xs[xbase + nt*8];
                    float xv1 = (float)(int)g_xs[xbase + nt*8 + 1];
                    float y0 = __fadd_rn(__fmul_rn(ra, xv0), __fmul_rn(rb, __fsub_rn(v0, zo)));
                    float y1 = __fadd_rn(__fmul_rn(ra, xv1), __fmul_rn(rb, __fsub_rn(v1, zo)));
                    float o0 = fminf(fmaxf(rintf(y0) + za, 0.f), 255.f);
                    float o1 = fminf(fmaxf(rintf(y1) + za, 0.f), 255.f);
                    int oc = ocw + nt*8 + cc;
                    out[((size_t)(n*CH + oc    )*HH + oh)*WW + ow] = o0;
                    out[((size_t)(n*CH + oc + 1)*HH + oh)*WW + ow] = o1;
                }
            }
        }
    }
}

// ---------------- launch ----------------
extern "C" void kernel_launch(void* const* d_in, const int* in_sizes, int n_in,
                              void* d_out, int out_size) {
    const float* x    = (const float*)d_in[0];
    const float* w1   = (const float*)d_in[1];
    const float* w2   = (const float*)d_in[2];
    const float* s_x  = (const float*)d_in[3];
    const float* z_x  = (const float*)d_in[4];
    const float* s_w1 = (const float*)d_in[5];
    const float* s_c1 = (const float*)d_in[6];
    const float* z_c1 = (const float*)d_in[7];
    const float* s_w2 = (const float*)d_in[8];
    const float* s_c2 = (const float*)d_in[9];
    const float* z_c2 = (const float*)d_in[10];
    const float* s_ad = (const float*)d_in[11];
    const float* z_ad = (const float*)d_in[12];
    float* out = (float*)d_out;

    cudaFuncSetAttribute(k_conv<0>, cudaFuncAttributeMaxDynamicSharedMemorySize, SMEM_TOTAL);
    cudaFuncSetAttribute(k_conv<1>, cudaFuncAttributeMaxDynamicSharedMemorySize, SMEM_TOTAL);

    unsigned islots = (unsigned)((size_t)NPIX_PAD * CH / 16);
    k_init<<<(islots + 255) / 256, 256>>>(z_c1);
    k_pack_x<<<NB * HH * WW, 256>>>(x, z_x);
    k_pack_w<<<9 * 256, 256>>>(w1, 0);
    k_pack_w<<<9 * 256, 256>>>(w2, 1);
    k_wsum<<<CH, 256>>>(w2);

    dim3 grid(NMT, 2);
    k_conv<0><<<grid, 256, SMEM_TOTAL>>>(s_x, s_w1, s_c1, z_c1, z_c1,
                                         s_x, s_ad, z_ad, nullptr);
    k_conv<1><<<grid, 256, SMEM_TOTAL>>>(s_c1, s_w2, s_c2, z_c2, z_c1,
                                         s_x, s_ad, z_ad, out);
}

// round 6
// speedup vs baseline: 2.2919x; 2.2919x over previous
#include <cuda_runtime.h>
#include <cuda_bf16.h>
#include <stdint.h>

// ---------------- problem constants ----------------
#define NB   64
#define CH   256
#define HH   28
#define WW   28
#define HPX  900              // 30*30 padded pixels per image
#define NPIX (NB*HPX)         // 57600
#define NPIX_PAD 57728        // slack for tap offsets on garbage rows
#define MT   256              // pixels (M) per CTA
#define NMT  (NPIX/MT)        // 225
#define NSTAGE 36             // 9 taps * 4 ic-chunks (64 ic each)
#define NBUF 4
#define A_BYTES 32768         // 256 rows * 128B (64 ic * bf16)
#define B_BYTES 16384         // 128 rows * 128B
#define STAGE_BYTES (A_BYTES + B_BYTES)        // 49152
#define SMEM_TOTAL (NBUF*STAGE_BYTES)          // 196608

// ---------------- device scratch (no cudaMalloc allowed) ----------------
__device__ __align__(16) __nv_bfloat16 g_axs [(size_t)NPIX_PAD*CH];  // x - z_x, pad 0
__device__ __align__(16) __nv_bfloat16 g_amid[(size_t)NPIX_PAD*CH];  // mid - z_c1, pad 0
__device__ __align__(16) __nv_bfloat16 g_wb1[9*CH*CH];               // [tap][oc][ic]
__device__ __align__(16) __nv_bfloat16 g_wb2[9*CH*CH];

// ---------------- PTX helpers ----------------
__device__ __forceinline__ uint32_t smem_u32(const void* p) {
    uint32_t a;
    asm("{ .reg .u64 t; cvta.to.shared.u64 t, %1; cvt.u32.u64 %0, t; }" : "=r"(a) : "l"(p));
    return a;
}
__device__ __forceinline__ void cp16(uint32_t sdst, const void* gsrc) {
    asm volatile("cp.async.cg.shared.global [%0], [%1], 16;" :: "r"(sdst), "l"(gsrc));
}
#define CP_COMMIT() asm volatile("cp.async.commit_group;" ::: "memory")
template <int N> __device__ __forceinline__ void cp_wait() {
    asm volatile("cp.async.wait_group %0;" :: "n"(N) : "memory");
}
__device__ __forceinline__ void ldm4(uint32_t* r, uint32_t addr) {
    asm volatile("ldmatrix.sync.aligned.m8n8.x4.shared.b16 {%0,%1,%2,%3}, [%4];"
        : "=r"(r[0]), "=r"(r[1]), "=r"(r[2]), "=r"(r[3]) : "r"(addr));
}
__device__ __forceinline__ void mma_bf16(float* d, const uint32_t* a, const uint32_t* b) {
    asm volatile("mma.sync.aligned.m16n8k16.row.col.f32.bf16.bf16.f32 "
        "{%0,%1,%2,%3},{%4,%5,%6,%7},{%8,%9},{%0,%1,%2,%3};"
        : "+f"(d[0]), "+f"(d[1]), "+f"(d[2]), "+f"(d[3])
        : "r"(a[0]), "r"(a[1]), "r"(a[2]), "r"(a[3]), "r"(b[0]), "r"(b[1]));
}

// ---------------- packing kernels ----------------
__global__ void k_zero() {
    size_t i = (size_t)blockIdx.x * blockDim.x + threadIdx.x;
    size_t per = (size_t)NPIX_PAD * CH * 2 / 16;          // int4 slots per array
    int4 z = make_int4(0, 0, 0, 0);
    if (i < per)            ((int4*)g_axs)[i]        = z;
    else if (i < 2 * per)   ((int4*)g_amid)[i - per] = z;
}

// x NCHW fp32 -> g_axs padded NHWC bf16 (x - z_x), smem transpose for coalescing
__global__ void k_pack_x(const float* __restrict__ x, const float* __restrict__ pzx) {
    __shared__ __nv_bfloat16 s[28 * 258];
    int n  = blockIdx.x / 28;
    int oh = blockIdx.x % 28;
    float zx = *pzx;
    for (int i = threadIdx.x; i < 28 * 256; i += 256) {
        int c = i / 28, ow = i % 28;
        float g = x[(((size_t)n * CH + c) * HH + oh) * WW + ow];
        s[ow * 258 + c] = __float2bfloat16(__fsub_rn(g, zx));
    }
    __syncthreads();
    for (int i = threadIdx.x; i < 28 * 256; i += 256) {
        int ow = i >> 8, c = i & 255;
        g_axs[((size_t)n * HPX + (oh + 1) * 30 + ow + 1) * CH + c] = s[ow * 258 + c];
    }
}

// w OIHW fp32 -> [tap][oc][ic] bf16
__global__ void k_pack_w(const float* __restrict__ w, int which) {
    int idx = blockIdx.x * blockDim.x + threadIdx.x;   // 9*256*256
    int ic  = idx & 255;
    int oc  = (idx >> 8) & 255;
    int tap = idx >> 16;
    __nv_bfloat16 v = __float2bfloat16(w[((size_t)oc * CH + ic) * 9 + tap]);
    if (which == 0) g_wb1[idx] = v; else g_wb2[idx] = v;
}

// ---------------- bf16 HMMA implicit-GEMM conv ----------------
// MODE 0: conv1, A = (x-z_x), writes g_amid = (mid - z_c1) bf16
// MODE 1: conv2, A = (mid - z_c1), fused residual qadd -> out fp32 NCHW
template <int MODE>
__global__ __launch_bounds__(512, 1) void k_conv(
    const float* __restrict__ ps_in,  const float* __restrict__ ps_w,
    const float* __restrict__ ps_out, const float* __restrict__ pz_out,
    const float* __restrict__ ps_x,   const float* __restrict__ ps_add,
    const float* __restrict__ pz_add,
    float* __restrict__ out)
{
    extern __shared__ char smem[];
    const uint32_t sb = smem_u32(smem);
    const __nv_bfloat16* act = (MODE == 0) ? g_axs : g_amid;
    const __nv_bfloat16* wq  = (MODE == 0) ? g_wb1 : g_wb2;

    const int tid  = threadIdx.x;
    const int lane = tid & 31;
    const int wid  = tid >> 5;
    const int wm   = wid & 3;           // 4 m-warps (64 px each)
    const int wn   = wid >> 2;          // 4 n-warps (32 oc each)
    const int P0   = blockIdx.x * MT;
    const int ocb  = blockIdx.y * 128;

    float acc[4][4][4];
#pragma unroll
    for (int mt = 0; mt < 4; mt++)
#pragma unroll
        for (int nt = 0; nt < 4; nt++)
#pragma unroll
            for (int j = 0; j < 4; j++) acc[mt][nt][j] = 0.f;

    // stage loader: tap = s/4, ic0 = (s%4)*64 ; A 2048 cp16 + B 1024 cp16
    auto load_stage = [&](int s) {
        int tap = s >> 2;
        int ic0 = (s & 3) * 64;
        int off = (tap / 3) * 30 + (tap % 3);
        uint32_t bufA = sb + (s % NBUF) * STAGE_BYTES;
        uint32_t bufB = bufA + A_BYTES;
        const char* ga = (const char*)act + (size_t)(P0 + off) * 512 + ic0 * 2;
        const char* gb = (const char*)wq + ((size_t)tap * 256 + ocb) * 512 + ic0 * 2;
#pragma unroll
        for (int i = 0; i < 4; i++) {
            int idx = tid + i * 512;            // 0..2047
            int row = idx >> 3, c16 = idx & 7;
            uint32_t sw = (uint32_t)(row * 128 + ((c16 ^ (row & 7)) << 4));
            cp16(bufA + sw, ga + (size_t)row * 512 + c16 * 16);
        }
#pragma unroll
        for (int i = 0; i < 2; i++) {
            int idx = tid + i * 512;            // 0..1023
            int row = idx >> 3, c16 = idx & 7;
            uint32_t sw = (uint32_t)(row * 128 + ((c16 ^ (row & 7)) << 4));
            cp16(bufB + sw, gb + (size_t)row * 512 + c16 * 16);
        }
        CP_COMMIT();
    };

    load_stage(0); load_stage(1); load_stage(2);

    // per-lane ldmatrix row/chunk selectors (x4: lanes 0-7 rows, 8-15 rows+8, 16-31 chunk+1)
    const int lrow = (lane & 7) + ((lane >> 3) & 1) * 8;
    const int lchk = lane >> 4;          // 0/1 -> k chunk within k16 group

#pragma unroll 1
    for (int s = 0; s < NSTAGE; s++) {
        if (s < NSTAGE - 2)      cp_wait<2>();
        else if (s == NSTAGE-2)  cp_wait<1>();
        else                     cp_wait<0>();
        __syncthreads();

        uint32_t bufA = sb + (s % NBUF) * STAGE_BYTES;
        uint32_t bufB = bufA + A_BYTES;
#pragma unroll
        for (int g = 0; g < 4; g++) {            // 4 k16 groups per 64-ic stage
            const int c = (g << 1) | lchk;       // 16B chunk index 0..7
            uint32_t af[4][4];
#pragma unroll
            for (int mt = 0; mt < 4; mt++) {
                int r = wm * 64 + mt * 16 + lrow;
                ldm4(af[mt], bufA + r * 128 + ((c ^ (r & 7)) << 4));
            }
            uint32_t bf[4][2];
#pragma unroll
            for (int nt2 = 0; nt2 < 2; nt2++) {
                int r = wn * 32 + nt2 * 16 + lrow;
                uint32_t rr[4];
                ldm4(rr, bufB + r * 128 + ((c ^ (r & 7)) << 4));
                bf[nt2*2][0]   = rr[0]; bf[nt2*2][1]   = rr[2];
                bf[nt2*2+1][0] = rr[1]; bf[nt2*2+1][1] = rr[3];
            }
#pragma unroll
            for (int mt = 0; mt < 4; mt++)
#pragma unroll
                for (int nt = 0; nt < 4; nt++)
                    mma_bf16(acc[mt][nt], af[mt], bf[nt]);
        }
        if (s + 3 < NSTAGE) load_stage(s + 3);
    }

    // ---------------- epilogue ----------------
    const float M  = __fdiv_rn(__fmul_rn(*ps_in, *ps_w), *ps_out);
    const float zo = *pz_out;
    const int qrow = lane >> 2;
    const int cc   = (lane & 3) << 1;
    const int ocw  = ocb + wn * 32;

    float ra = 0.f, rb = 0.f, za = 0.f;
    if (MODE == 1) {
        ra = __fdiv_rn(*ps_x,   *ps_add);
        rb = __fdiv_rn(*ps_out, *ps_add);
        za = *pz_add;
    }

#pragma unroll
    for (int mt = 0; mt < 4; mt++) {
#pragma unroll
        for (int h = 0; h < 2; h++) {
            int r  = wm * 64 + mt * 16 + qrow + h * 8;
            int P  = P0 + r;
            int n  = P / HPX;
            int q  = P - n * HPX;
            int oh = q / 30, ow = q - oh * 30;
            if (oh >= 28 || ow >= 28) continue;

            if (MODE == 0) {
                size_t base = (size_t)(P + 31) * 256 + ocw + cc;
#pragma unroll
                for (int nt = 0; nt < 4; nt++) {
                    float v0 = rintf(__fmul_rn(M, acc[mt][nt][h*2]))   + zo;
                    float v1 = rintf(__fmul_rn(M, acc[mt][nt][h*2+1])) + zo;
                    v0 = fminf(fmaxf(v0, 0.f), 255.f);
                    v1 = fminf(fmaxf(v1, 0.f), 255.f);
                    __nv_bfloat162 u;
                    u.x = __float2bfloat16(v0 - zo);
                    u.y = __float2bfloat16(v1 - zo);
                    *(__nv_bfloat162*)(g_amid + base + nt * 8) = u;
                }
            } else {
                size_t xbase = (size_t)(P + 31) * 256 + ocw + cc;
#pragma unroll
                for (int nt = 0; nt < 4; nt++) {
                    float v0 = rintf(__fmul_rn(M, acc[mt][nt][h*2]))   + zo;
                    float v1 = rintf(__fmul_rn(M, acc[mt][nt][h*2+1])) + zo;
                    v0 = fminf(fmaxf(v0, 0.f), 255.f);
                    v1 = fminf(fmaxf(v1, 0.f), 255.f);
                    float xv0 = __bfloat162float(g_axs[xbase + nt * 8]);
                    float xv1 = __bfloat162float(g_axs[xbase + nt * 8 + 1]);
                    float y0 = __fadd_rn(__fmul_rn(ra, xv0), __fmul_rn(rb, __fsub_rn(v0, zo)));
                    float y1 = __fadd_rn(__fmul_rn(ra, xv1), __fmul_rn(rb, __fsub_rn(v1, zo)));
                    float o0 = fminf(fmaxf(rintf(y0) + za, 0.f), 255.f);
                    float o1 = fminf(fmaxf(rintf(y1) + za, 0.f), 255.f);
                    int oc = ocw + nt * 8 + cc;
                    out[((size_t)(n * CH + oc    ) * HH + oh) * WW + ow] = o0;
                    out[((size_t)(n * CH + oc + 1) * HH + oh) * WW + ow] = o1;
                }
            }
        }
    }
}

// ---------------- launch ----------------
extern "C" void kernel_launch(void* const* d_in, const int* in_sizes, int n_in,
                              void* d_out, int out_size) {
    const float* x    = (const float*)d_in[0];
    const float* w1   = (const float*)d_in[1];
    const float* w2   = (const float*)d_in[2];
    const float* s_x  = (const float*)d_in[3];
    const float* z_x  = (const float*)d_in[4];
    const float* s_w1 = (const float*)d_in[5];
    const float* s_c1 = (const float*)d_in[6];
    const float* z_c1 = (const float*)d_in[7];
    const float* s_w2 = (const float*)d_in[8];
    const float* s_c2 = (const float*)d_in[9];
    const float* z_c2 = (const float*)d_in[10];
    const float* s_ad = (const float*)d_in[11];
    const float* z_ad = (const float*)d_in[12];
    float* out = (float*)d_out;

    cudaFuncSetAttribute(k_conv<0>, cudaFuncAttributeMaxDynamicSharedMemorySize, SMEM_TOTAL);
    cudaFuncSetAttribute(k_conv<1>, cudaFuncAttributeMaxDynamicSharedMemorySize, SMEM_TOTAL);

    size_t zslots = 2 * ((size_t)NPIX_PAD * CH * 2 / 16);
    k_zero<<<(unsigned)((zslots + 255) / 256), 256>>>();
    k_pack_x<<<NB * HH, 256>>>(x, z_x);
    k_pack_w<<<9 * 256, 256>>>(w1, 0);
    k_pack_w<<<9 * 256, 256>>>(w2, 1);

    dim3 grid(NMT, 2);
    k_conv<0><<<grid, 512, SMEM_TOTAL>>>(s_x, s_w1, s_c1, z_c1,
                                         s_x, s_ad, z_ad, nullptr);
    k_conv<1><<<grid, 512, SMEM_TOTAL>>>(s_c1, s_w2, s_c2, z_c2,
                                         s_x, s_ad, z_ad, out);
}

// round 7
// speedup vs baseline: 2.3593x; 1.0294x over previous
#include <cuda_runtime.h>
#include <cuda_bf16.h>
#include <stdint.h>

// ---------------- problem constants ----------------
#define NB   64
#define CH   256
#define HH   28
#define WW   28
#define HPX  900              // 30*30 padded pixels per image
#define NPIX (NB*HPX)         // 57600
#define NPIX_PAD 57728        // slack for tap offsets on garbage rows
#define MT   128              // pixels (M) per CTA
#define NMT  (NPIX/MT)        // 450
#define NSTAGE 36             // 9 taps * 4 ic-chunks (64 ic each)
#define NBUF 4
#define A_BYTES 16384         // 128 rows * 128B
#define B_BYTES 32768         // 256 rows * 128B
#define STAGE_BYTES (A_BYTES + B_BYTES)        // 49152
#define SMEM_TOTAL (NBUF*STAGE_BYTES)          // 196608

// ---------------- device scratch (no cudaMalloc allowed) ----------------
__device__ __align__(16) __nv_bfloat16 g_axs [(size_t)NPIX_PAD*CH];  // x - z_x, pad 0
__device__ __align__(16) __nv_bfloat16 g_amid[(size_t)NPIX_PAD*CH];  // mid - z_c1, pad 0
__device__ __align__(16) __nv_bfloat16 g_wb1[9*CH*CH];               // [tap][oc][ic]
__device__ __align__(16) __nv_bfloat16 g_wb2[9*CH*CH];

// ---------------- PTX helpers ----------------
__device__ __forceinline__ uint32_t smem_u32(const void* p) {
    uint32_t a;
    asm("{ .reg .u64 t; cvta.to.shared.u64 t, %1; cvt.u32.u64 %0, t; }" : "=r"(a) : "l"(p));
    return a;
}
__device__ __forceinline__ void cp16(uint32_t sdst, const void* gsrc) {
    asm volatile("cp.async.cg.shared.global [%0], [%1], 16;" :: "r"(sdst), "l"(gsrc));
}
#define CP_COMMIT() asm volatile("cp.async.commit_group;" ::: "memory")
template <int N> __device__ __forceinline__ void cp_wait() {
    asm volatile("cp.async.wait_group %0;" :: "n"(N) : "memory");
}
__device__ __forceinline__ void ldm4(uint32_t* r, uint32_t addr) {
    asm volatile("ldmatrix.sync.aligned.m8n8.x4.shared.b16 {%0,%1,%2,%3}, [%4];"
        : "=r"(r[0]), "=r"(r[1]), "=r"(r[2]), "=r"(r[3]) : "r"(addr));
}
__device__ __forceinline__ void mma_bf16(float* d, const uint32_t* a, const uint32_t* b) {
    asm volatile("mma.sync.aligned.m16n8k16.row.col.f32.bf16.bf16.f32 "
        "{%0,%1,%2,%3},{%4,%5,%6,%7},{%8,%9},{%0,%1,%2,%3};"
        : "+f"(d[0]), "+f"(d[1]), "+f"(d[2]), "+f"(d[3])
        : "r"(a[0]), "r"(a[1]), "r"(a[2]), "r"(a[3]), "r"(b[0]), "r"(b[1]));
}

// ---------------- packing kernels ----------------
// zero ONLY the padding ring + M-slack of both activation arrays (interior is
// overwritten by k_pack_x / conv1 epilogue). 116 ring px/img + 128 slack px.
#define RING_SLOTS (64*116 + 128)       // 7552 pixel slots
__global__ void k_zero_halo() {
    int idx = blockIdx.x * blockDim.x + threadIdx.x;   // RING_SLOTS*32 int4 per array
    int total = RING_SLOTS * 32;
    if (idx >= 2 * total) return;
    int arr = idx >= total;
    int t = arr ? idx - total : idx;
    int chunk = t & 31;            // 32 int4 per 512B pixel
    int slot  = t >> 5;
    size_t P;
    if (slot < 64 * 116) {
        int img = slot / 116, i = slot % 116;
        int q;
        if (i < 30)       q = i;                       // row 0
        else if (i < 60)  q = 870 + (i - 30);          // row 29
        else if (i < 88)  q = (i - 60 + 1) * 30;       // col 0, rows 1..28
        else              q = (i - 88 + 1) * 30 + 29;  // col 29, rows 1..28
        P = (size_t)img * HPX + q;
    } else {
        P = (size_t)NPIX + (slot - 64 * 116);          // slack rows
    }
    int4 z = make_int4(0, 0, 0, 0);
    if (arr == 0) ((int4*)(g_axs  + P * 256))[chunk] = z;
    else          ((int4*)(g_amid + P * 256))[chunk] = z;
}

// x NCHW fp32 -> g_axs padded NHWC bf16 (x - z_x), smem transpose for coalescing
__global__ void k_pack_x(const float* __restrict__ x, const float* __restrict__ pzx) {
    __shared__ __nv_bfloat16 s[28 * 258];
    int n  = blockIdx.x / 28;
    int oh = blockIdx.x % 28;
    float zx = *pzx;
    for (int i = threadIdx.x; i < 28 * 256; i += 256) {
        int c = i / 28, ow = i % 28;
        float g = x[(((size_t)n * CH + c) * HH + oh) * WW + ow];
        s[ow * 258 + c] = __float2bfloat16(__fsub_rn(g, zx));
    }
    __syncthreads();
    for (int i = threadIdx.x; i < 28 * 256; i += 256) {
        int ow = i >> 8, c = i & 255;
        g_axs[((size_t)n * HPX + (oh + 1) * 30 + ow + 1) * CH + c] = s[ow * 258 + c];
    }
}

// w OIHW fp32 -> [tap][oc][ic] bf16
__global__ void k_pack_w(const float* __restrict__ w, int which) {
    int idx = blockIdx.x * blockDim.x + threadIdx.x;   // 9*256*256
    int ic  = idx & 255;
    int oc  = (idx >> 8) & 255;
    int tap = idx >> 16;
    __nv_bfloat16 v = __float2bfloat16(w[((size_t)oc * CH + ic) * 9 + tap]);
    if (which == 0) g_wb1[idx] = v; else g_wb2[idx] = v;
}

// ---------------- bf16 HMMA implicit-GEMM conv ----------------
// CTA tile: 128 px x 256 oc; 8 warps, warp tile 64 px x 64 oc.
// MODE 0: conv1, A = (x-z_x), writes g_amid = (mid - z_c1) bf16
// MODE 1: conv2, A = (mid - z_c1), fused residual qadd -> out fp32 NCHW
template <int MODE>
__global__ __launch_bounds__(256, 1) void k_conv(
    const float* __restrict__ ps_in,  const float* __restrict__ ps_w,
    const float* __restrict__ ps_out, const float* __restrict__ pz_out,
    const float* __restrict__ ps_x,   const float* __restrict__ ps_add,
    const float* __restrict__ pz_add,
    float* __restrict__ out)
{
    extern __shared__ char smem[];
    const uint32_t sb = smem_u32(smem);
    const __nv_bfloat16* act = (MODE == 0) ? g_axs : g_amid;
    const __nv_bfloat16* wq  = (MODE == 0) ? g_wb1 : g_wb2;

    const int tid  = threadIdx.x;
    const int lane = tid & 31;
    const int wid  = tid >> 5;
    const int wm   = wid & 1;           // 2 m-warps (64 px each)
    const int wn   = wid >> 1;          // 4 n-warps (64 oc each)
    const int P0   = blockIdx.x * MT;

    float acc[4][8][4];
#pragma unroll
    for (int mt = 0; mt < 4; mt++)
#pragma unroll
        for (int nt = 0; nt < 8; nt++)
#pragma unroll
            for (int j = 0; j < 4; j++) acc[mt][nt][j] = 0.f;

    // stage loader: tap = s/4, ic0 = (s%4)*64 ; A 1024 cp16 + B 2048 cp16
    auto load_stage = [&](int s) {
        int tap = s >> 2;
        int ic0 = (s & 3) * 64;
        int off = (tap / 3) * 30 + (tap % 3);
        uint32_t bufA = sb + (s % NBUF) * STAGE_BYTES;
        uint32_t bufB = bufA + A_BYTES;
        const char* ga = (const char*)act + (size_t)(P0 + off) * 512 + ic0 * 2;
        const char* gb = (const char*)wq + (size_t)tap * 256 * 512 + ic0 * 2;
#pragma unroll
        for (int i = 0; i < 4; i++) {
            int idx = tid + i * 256;            // 0..1023
            int row = idx >> 3, c16 = idx & 7;
            uint32_t sw = (uint32_t)(row * 128 + ((c16 ^ (row & 7)) << 4));
            cp16(bufA + sw, ga + (size_t)row * 512 + c16 * 16);
        }
#pragma unroll
        for (int i = 0; i < 8; i++) {
            int idx = tid + i * 256;            // 0..2047
            int row = idx >> 3, c16 = idx & 7;
            uint32_t sw = (uint32_t)(row * 128 + ((c16 ^ (row & 7)) << 4));
            cp16(bufB + sw, gb + (size_t)row * 512 + c16 * 16);
        }
        CP_COMMIT();
    };

    load_stage(0); load_stage(1); load_stage(2);

    // per-lane ldmatrix row/chunk selectors
    const int lrow = (lane & 7) + ((lane >> 3) & 1) * 8;
    const int lchk = lane >> 4;          // 0/1 -> 16B chunk within k16 group

#pragma unroll 1
    for (int s = 0; s < NSTAGE; s++) {
        if (s < NSTAGE - 2)      cp_wait<2>();
        else if (s == NSTAGE-2)  cp_wait<1>();
        else                     cp_wait<0>();
        __syncthreads();

        uint32_t bufA = sb + (s % NBUF) * STAGE_BYTES;
        uint32_t bufB = bufA + A_BYTES;
#pragma unroll
        for (int g = 0; g < 4; g++) {            // 4 k16 groups per 64-ic stage
            const int c = (g << 1) | lchk;       // 16B chunk index 0..7
            uint32_t af[4][4];
#pragma unroll
            for (int mt = 0; mt < 4; mt++) {
                int r = wm * 64 + mt * 16 + lrow;
                ldm4(af[mt], bufA + r * 128 + ((c ^ (r & 7)) << 4));
            }
            uint32_t bf[8][2];
#pragma unroll
            for (int nt2 = 0; nt2 < 4; nt2++) {
                int r = wn * 64 + nt2 * 16 + lrow;
                uint32_t rr[4];
                ldm4(rr, bufB + r * 128 + ((c ^ (r & 7)) << 4));
                bf[nt2*2][0]   = rr[0]; bf[nt2*2][1]   = rr[2];
                bf[nt2*2+1][0] = rr[1]; bf[nt2*2+1][1] = rr[3];
            }
#pragma unroll
            for (int mt = 0; mt < 4; mt++)
#pragma unroll
                for (int nt = 0; nt < 8; nt++)
                    mma_bf16(acc[mt][nt], af[mt], bf[nt]);
        }
        if (s + 3 < NSTAGE) load_stage(s + 3);
    }

    // ---------------- epilogue ----------------
    const float M  = __fdiv_rn(__fmul_rn(*ps_in, *ps_w), *ps_out);
    const float zo = *pz_out;
    const int qrow = lane >> 2;
    const int cc   = (lane & 3) << 1;
    const int ocw  = wn * 64;

    float ra = 0.f, rb = 0.f, za = 0.f;
    if (MODE == 1) {
        ra = __fdiv_rn(*ps_x,   *ps_add);
        rb = __fdiv_rn(*ps_out, *ps_add);
        za = *pz_add;
    }

#pragma unroll
    for (int mt = 0; mt < 4; mt++) {
#pragma unroll
        for (int h = 0; h < 2; h++) {
            int r  = wm * 64 + mt * 16 + qrow + h * 8;
            int P  = P0 + r;
            int n  = P / HPX;
            int q  = P - n * HPX;
            int oh = q / 30, ow = q - oh * 30;
            if (oh >= 28 || ow >= 28) continue;

            if (MODE == 0) {
                size_t base = (size_t)(P + 31) * 256 + ocw + cc;
#pragma unroll
                for (int nt = 0; nt < 8; nt++) {
                    float v0 = rintf(__fmul_rn(M, acc[mt][nt][h*2]))   + zo;
                    float v1 = rintf(__fmul_rn(M, acc[mt][nt][h*2+1])) + zo;
                    v0 = fminf(fmaxf(v0, 0.f), 255.f);
                    v1 = fminf(fmaxf(v1, 0.f), 255.f);
                    __nv_bfloat162 u;
                    u.x = __float2bfloat16(v0 - zo);
                    u.y = __float2bfloat16(v1 - zo);
                    *(__nv_bfloat162*)(g_amid + base + nt * 8) = u;
                }
            } else {
                size_t xbase = (size_t)(P + 31) * 256 + ocw + cc;
#pragma unroll
                for (int nt = 0; nt < 8; nt++) {
                    float v0 = rintf(__fmul_rn(M, acc[mt][nt][h*2]))   + zo;
                    float v1 = rintf(__fmul_rn(M, acc[mt][nt][h*2+1])) + zo;
                    v0 = fminf(fmaxf(v0, 0.f), 255.f);
                    v1 = fminf(fmaxf(v1, 0.f), 255.f);
                    float xv0 = __bfloat162float(g_axs[xbase + nt * 8]);
                    float xv1 = __bfloat162float(g_axs[xbase + nt * 8 + 1]);
                    float y0 = __fadd_rn(__fmul_rn(ra, xv0), __fmul_rn(rb, __fsub_rn(v0, zo)));
                    float y1 = __fadd_rn(__fmul_rn(ra, xv1), __fmul_rn(rb, __fsub_rn(v1, zo)));
                    float o0 = fminf(fmaxf(rintf(y0) + za, 0.f), 255.f);
                    float o1 = fminf(fmaxf(rintf(y1) + za, 0.f), 255.f);
                    int oc = ocw + nt * 8 + cc;
                    out[((size_t)(n * CH + oc    ) * HH + oh) * WW + ow] = o0;
                    out[((size_t)(n * CH + oc + 1) * HH + oh) * WW + ow] = o1;
                }
            }
        }
    }
}

// ---------------- launch ----------------
extern "C" void kernel_launch(void* const* d_in, const int* in_sizes, int n_in,
                              void* d_out, int out_size) {
    const float* x    = (const float*)d_in[0];
    const float* w1   = (const float*)d_in[1];
    const float* w2   = (const float*)d_in[2];
    const float* s_x  = (const float*)d_in[3];
    const float* z_x  = (const float*)d_in[4];
    const float* s_w1 = (const float*)d_in[5];
    const float* s_c1 = (const float*)d_in[6];
    const float* z_c1 = (const float*)d_in[7];
    const float* s_w2 = (const float*)d_in[8];
    const float* s_c2 = (const float*)d_in[9];
    const float* z_c2 = (const float*)d_in[10];
    const float* s_ad = (const float*)d_in[11];
    const float* z_ad = (const float*)d_in[12];
    float* out = (float*)d_out;

    cudaFuncSetAttribute(k_conv<0>, cudaFuncAttributeMaxDynamicSharedMemorySize, SMEM_TOTAL);
    cudaFuncSetAttribute(k_conv<1>, cudaFuncAttributeMaxDynamicSharedMemorySize, SMEM_TOTAL);

    int zthreads = 2 * RING_SLOTS * 32;
    k_zero_halo<<<(zthreads + 255) / 256, 256>>>();
    k_pack_x<<<NB * HH, 256>>>(x, z_x);
    k_pack_w<<<9 * 256, 256>>>(w1, 0);
    k_pack_w<<<9 * 256, 256>>>(w2, 1);

    k_conv<0><<<NMT, 256, SMEM_TOTAL>>>(s_x, s_w1, s_c1, z_c1,
                                        s_x, s_ad, z_ad, nullptr);
    k_conv<1><<<NMT, 256, SMEM_TOTAL>>>(s_c1, s_w2, s_c2, z_c2,
                                        s_x, s_ad, z_ad, out);
}

// round 8
// speedup vs baseline: 2.4634x; 1.0441x over previous
#include <cuda_runtime.h>
#include <cuda_bf16.h>
#include <stdint.h>

// ---------------- problem constants ----------------
#define NB   64
#define CH   256
#define HH   28
#define WW   28
#define HPX  900              // 30*30 padded pixels per image
#define NPIX (NB*HPX)         // 57600
#define NPIX_PAD 57728        // slack for tap offsets on garbage rows
#define MT   128              // pixels (M) per CTA
#define NMT  (NPIX/MT)        // 450
#define NSTAGE 36             // 9 taps * 4 ic-chunks (64 ic each)
#define NBUF 3
#define A_BYTES 16384         // 128 rows * 128B
#define B_BYTES 16384         // 128 rows * 128B
#define STAGE_BYTES (A_BYTES + B_BYTES)        // 32768
#define SMEM_TOTAL (NBUF*STAGE_BYTES)          // 98304 -> 2 CTAs/SM

// ---------------- device scratch (no cudaMalloc allowed) ----------------
__device__ __align__(16) __nv_bfloat16 g_axs [(size_t)NPIX_PAD*CH];  // x - z_x, pad 0
__device__ __align__(16) __nv_bfloat16 g_amid[(size_t)NPIX_PAD*CH];  // mid - z_c1, pad 0
__device__ __align__(16) __nv_bfloat16 g_wb1[9*CH*CH];               // [tap][oc][ic]
__device__ __align__(16) __nv_bfloat16 g_wb2[9*CH*CH];

// ---------------- PTX helpers ----------------
__device__ __forceinline__ uint32_t smem_u32(const void* p) {
    uint32_t a;
    asm("{ .reg .u64 t; cvta.to.shared.u64 t, %1; cvt.u32.u64 %0, t; }" : "=r"(a) : "l"(p));
    return a;
}
__device__ __forceinline__ void cp16(uint32_t sdst, const void* gsrc) {
    asm volatile("cp.async.cg.shared.global [%0], [%1], 16;" :: "r"(sdst), "l"(gsrc));
}
#define CP_COMMIT() asm volatile("cp.async.commit_group;" ::: "memory")
template <int N> __device__ __forceinline__ void cp_wait() {
    asm volatile("cp.async.wait_group %0;" :: "n"(N) : "memory");
}
__device__ __forceinline__ void ldm4(uint32_t* r, uint32_t addr) {
    asm volatile("ldmatrix.sync.aligned.m8n8.x4.shared.b16 {%0,%1,%2,%3}, [%4];"
        : "=r"(r[0]), "=r"(r[1]), "=r"(r[2]), "=r"(r[3]) : "r"(addr));
}
__device__ __forceinline__ void mma_bf16(float* d, const uint32_t* a, const uint32_t* b) {
    asm volatile("mma.sync.aligned.m16n8k16.row.col.f32.bf16.bf16.f32 "
        "{%0,%1,%2,%3},{%4,%5,%6,%7},{%8,%9},{%0,%1,%2,%3};"
        : "+f"(d[0]), "+f"(d[1]), "+f"(d[2]), "+f"(d[3])
        : "r"(a[0]), "r"(a[1]), "r"(a[2]), "r"(a[3]), "r"(b[0]), "r"(b[1]));
}

// ---------------- packing kernels ----------------
// zero ONLY padding ring + M-slack (interior fully overwritten later)
#define RING_SLOTS (64*116 + 128)       // 7552 pixel slots
__global__ void k_zero_halo() {
    int idx = blockIdx.x * blockDim.x + threadIdx.x;
    int total = RING_SLOTS * 32;
    if (idx >= 2 * total) return;
    int arr = idx >= total;
    int t = arr ? idx - total : idx;
    int chunk = t & 31;
    int slot  = t >> 5;
    size_t P;
    if (slot < 64 * 116) {
        int img = slot / 116, i = slot % 116;
        int q;
        if (i < 30)       q = i;
        else if (i < 60)  q = 870 + (i - 30);
        else if (i < 88)  q = (i - 60 + 1) * 30;
        else              q = (i - 88 + 1) * 30 + 29;
        P = (size_t)img * HPX + q;
    } else {
        P = (size_t)NPIX + (slot - 64 * 116);
    }
    int4 z = make_int4(0, 0, 0, 0);
    if (arr == 0) ((int4*)(g_axs  + P * 256))[chunk] = z;
    else          ((int4*)(g_amid + P * 256))[chunk] = z;
}

// x NCHW fp32 -> g_axs padded NHWC bf16 (x - z_x), smem transpose
__global__ void k_pack_x(const float* __restrict__ x, const float* __restrict__ pzx) {
    __shared__ __nv_bfloat16 s[28 * 258];
    int n  = blockIdx.x / 28;
    int oh = blockIdx.x % 28;
    float zx = *pzx;
    for (int i = threadIdx.x; i < 28 * 256; i += 256) {
        int c = i / 28, ow = i % 28;
        float g = x[(((size_t)n * CH + c) * HH + oh) * WW + ow];
        s[ow * 258 + c] = __float2bfloat16(__fsub_rn(g, zx));
    }
    __syncthreads();
    for (int i = threadIdx.x; i < 28 * 256; i += 256) {
        int ow = i >> 8, c = i & 255;
        g_axs[((size_t)n * HPX + (oh + 1) * 30 + ow + 1) * CH + c] = s[ow * 258 + c];
    }
}

// both weights OIHW fp32 -> [tap][oc][ic] bf16 in one kernel
__global__ void k_pack_w2(const float* __restrict__ w1, const float* __restrict__ w2) {
    int idx = blockIdx.x * blockDim.x + threadIdx.x;   // 2 * 9*256*256
    int which = idx >= 9*256*256;
    int j = which ? idx - 9*256*256 : idx;
    int ic  = j & 255;
    int oc  = (j >> 8) & 255;
    int tap = j >> 16;
    const float* w = which ? w2 : w1;
    __nv_bfloat16 v = __float2bfloat16(w[((size_t)oc * CH + ic) * 9 + tap]);
    if (which == 0) g_wb1[j] = v; else g_wb2[j] = v;
}

// ---------------- bf16 HMMA implicit-GEMM conv ----------------
// CTA tile: 128 px x 128 oc; 4 warps, warp tile 64 px x 64 oc; 2 CTAs/SM.
// MODE 0: conv1, A = (x-z_x), writes g_amid = (mid - z_c1) bf16
// MODE 1: conv2, A = (mid - z_c1), fused residual qadd -> out fp32 NCHW
template <int MODE>
__global__ __launch_bounds__(128, 2) void k_conv(
    const float* __restrict__ ps_in,  const float* __restrict__ ps_w,
    const float* __restrict__ ps_out, const float* __restrict__ pz_out,
    const float* __restrict__ ps_x,   const float* __restrict__ ps_add,
    const float* __restrict__ pz_add,
    float* __restrict__ out)
{
    extern __shared__ char smem[];
    const uint32_t sb = smem_u32(smem);
    const __nv_bfloat16* act = (MODE == 0) ? g_axs : g_amid;
    const __nv_bfloat16* wq  = (MODE == 0) ? g_wb1 : g_wb2;

    const int tid  = threadIdx.x;
    const int lane = tid & 31;
    const int wid  = tid >> 5;
    const int wm   = wid & 1;           // 2 m-warps (64 px each)
    const int wn   = wid >> 1;          // 2 n-warps (64 oc each)
    const int P0   = blockIdx.x * MT;
    const int ocb  = blockIdx.y * 128;

    float acc[4][8][4];
#pragma unroll
    for (int mt = 0; mt < 4; mt++)
#pragma unroll
        for (int nt = 0; nt < 8; nt++)
#pragma unroll
            for (int j = 0; j < 4; j++) acc[mt][nt][j] = 0.f;

    // stage loader: tap = s/4, ic0 = (s%4)*64 ; A 1024 cp16 + B 1024 cp16, 128 thr
    auto load_stage = [&](int s) {
        int tap = s >> 2;
        int ic0 = (s & 3) * 64;
        int off = (tap / 3) * 30 + (tap % 3);
        uint32_t bufA = sb + (s % NBUF) * STAGE_BYTES;
        uint32_t bufB = bufA + A_BYTES;
        const char* ga = (const char*)act + (size_t)(P0 + off) * 512 + ic0 * 2;
        const char* gb = (const char*)wq + ((size_t)tap * 256 + ocb) * 512 + ic0 * 2;
#pragma unroll
        for (int i = 0; i < 8; i++) {
            int idx = tid + i * 128;            // 0..1023
            int row = idx >> 3, c16 = idx & 7;
            uint32_t sw = (uint32_t)(row * 128 + ((c16 ^ (row & 7)) << 4));
            cp16(bufA + sw, ga + (size_t)row * 512 + c16 * 16);
        }
#pragma unroll
        for (int i = 0; i < 8; i++) {
            int idx = tid + i * 128;
            int row = idx >> 3, c16 = idx & 7;
            uint32_t sw = (uint32_t)(row * 128 + ((c16 ^ (row & 7)) << 4));
            cp16(bufB + sw, gb + (size_t)row * 512 + c16 * 16);
        }
        CP_COMMIT();
    };

    load_stage(0); load_stage(1);

    // per-lane ldmatrix row/chunk selectors
    const int lrow = (lane & 7) + ((lane >> 3) & 1) * 8;
    const int lchk = lane >> 4;          // 0/1 -> 16B chunk within k16 group

#pragma unroll 1
    for (int s = 0; s < NSTAGE; s++) {
        if (s == NSTAGE - 1) cp_wait<0>(); else cp_wait<1>();
        __syncthreads();

        uint32_t bufA = sb + (s % NBUF) * STAGE_BYTES;
        uint32_t bufB = bufA + A_BYTES;

        if (s + 2 < NSTAGE) load_stage(s + 2);

#pragma unroll
        for (int g = 0; g < 4; g++) {            // 4 k16 groups per 64-ic stage
            const int c = (g << 1) | lchk;       // 16B chunk index 0..7
            uint32_t af[4][4];
#pragma unroll
            for (int mt = 0; mt < 4; mt++) {
                int r = wm * 64 + mt * 16 + lrow;
                ldm4(af[mt], bufA + r * 128 + ((c ^ (r & 7)) << 4));
            }
            uint32_t bf[8][2];
#pragma unroll
            for (int nt2 = 0; nt2 < 4; nt2++) {
                int r = wn * 64 + nt2 * 16 + lrow;
                uint32_t rr[4];
                ldm4(rr, bufB + r * 128 + ((c ^ (r & 7)) << 4));
                bf[nt2*2][0]   = rr[0]; bf[nt2*2][1]   = rr[2];
                bf[nt2*2+1][0] = rr[1]; bf[nt2*2+1][1] = rr[3];
            }
#pragma unroll
            for (int mt = 0; mt < 4; mt++)
#pragma unroll
                for (int nt = 0; nt < 8; nt++)
                    mma_bf16(acc[mt][nt], af[mt], bf[nt]);
        }
    }

    // ---------------- epilogue ----------------
    const float M  = __fdiv_rn(__fmul_rn(*ps_in, *ps_w), *ps_out);
    const float zo = *pz_out;
    const int qrow = lane >> 2;
    const int cc   = (lane & 3) << 1;
    const int ocw  = ocb + wn * 64;

    float ra = 0.f, rb = 0.f, za = 0.f;
    if (MODE == 1) {
        ra = __fdiv_rn(*ps_x,   *ps_add);
        rb = __fdiv_rn(*ps_out, *ps_add);
        za = *pz_add;
    }

#pragma unroll
    for (int mt = 0; mt < 4; mt++) {
#pragma unroll
        for (int h = 0; h < 2; h++) {
            int r  = wm * 64 + mt * 16 + qrow + h * 8;
            int P  = P0 + r;
            int n  = P / HPX;
            int q  = P - n * HPX;
            int oh = q / 30, ow = q - oh * 30;
            if (oh >= 28 || ow >= 28) continue;

            if (MODE == 0) {
                size_t base = (size_t)(P + 31) * 256 + ocw + cc;
#pragma unroll
                for (int nt = 0; nt < 8; nt++) {
                    float v0 = rintf(__fmul_rn(M, acc[mt][nt][h*2]))   + zo;
                    float v1 = rintf(__fmul_rn(M, acc[mt][nt][h*2+1])) + zo;
                    v0 = fminf(fmaxf(v0, 0.f), 255.f);
                    v1 = fminf(fmaxf(v1, 0.f), 255.f);
                    __nv_bfloat162 u;
                    u.x = __float2bfloat16(v0 - zo);
                    u.y = __float2bfloat16(v1 - zo);
                    *(__nv_bfloat162*)(g_amid + base + nt * 8) = u;
                }
            } else {
                size_t xbase = (size_t)(P + 31) * 256 + ocw + cc;
#pragma unroll
                for (int nt = 0; nt < 8; nt++) {
                    float v0 = rintf(__fmul_rn(M, acc[mt][nt][h*2]))   + zo;
                    float v1 = rintf(__fmul_rn(M, acc[mt][nt][h*2+1])) + zo;
                    v0 = fminf(fmaxf(v0, 0.f), 255.f);
                    v1 = fminf(fmaxf(v1, 0.f), 255.f);
                    float xv0 = __bfloat162float(g_axs[xbase + nt * 8]);
                    float xv1 = __bfloat162float(g_axs[xbase + nt * 8 + 1]);
                    float y0 = __fadd_rn(__fmul_rn(ra, xv0), __fmul_rn(rb, __fsub_rn(v0, zo)));
                    float y1 = __fadd_rn(__fmul_rn(ra, xv1), __fmul_rn(rb, __fsub_rn(v1, zo)));
                    float o0 = fminf(fmaxf(rintf(y0) + za, 0.f), 255.f);
                    float o1 = fminf(fmaxf(rintf(y1) + za, 0.f), 255.f);
                    int oc = ocw + nt * 8 + cc;
                    out[((size_t)(n * CH + oc    ) * HH + oh) * WW + ow] = o0;
                    out[((size_t)(n * CH + oc + 1) * HH + oh) * WW + ow] = o1;
                }
            }
        }
    }
}

// ---------------- launch ----------------
extern "C" void kernel_launch(void* const* d_in, const int* in_sizes, int n_in,
                              void* d_out, int out_size) {
    const float* x    = (const float*)d_in[0];
    const float* w1   = (const float*)d_in[1];
    const float* w2   = (const float*)d_in[2];
    const float* s_x  = (const float*)d_in[3];
    const float* z_x  = (const float*)d_in[4];
    const float* s_w1 = (const float*)d_in[5];
    const float* s_c1 = (const float*)d_in[6];
    const float* z_c1 = (const float*)d_in[7];
    const float* s_w2 = (const float*)d_in[8];
    const float* s_c2 = (const float*)d_in[9];
    const float* z_c2 = (const float*)d_in[10];
    const float* s_ad = (const float*)d_in[11];
    const float* z_ad = (const float*)d_in[12];
    float* out = (float*)d_out;

    cudaFuncSetAttribute(k_conv<0>, cudaFuncAttributeMaxDynamicSharedMemorySize, SMEM_TOTAL);
    cudaFuncSetAttribute(k_conv<1>, cudaFuncAttributeMaxDynamicSharedMemorySize, SMEM_TOTAL);

    int zthreads = 2 * RING_SLOTS * 32;
    k_zero_halo<<<(zthreads + 255) / 256, 256>>>();
    k_pack_x<<<NB * HH, 256>>>(x, z_x);
    k_pack_w2<<<2 * 9 * 256, 256>>>(w1, w2);

    dim3 grid(NMT, 2);
    k_conv<0><<<grid, 128, SMEM_TOTAL>>>(s_x, s_w1, s_c1, z_c1,
                                         s_x, s_ad, z_ad, nullptr);
    k_conv<1><<<grid, 128, SMEM_TOTAL>>>(s_c1, s_w2, s_c2, z_c2,
                                         s_x, s_ad, z_ad, out);
}

// round 9
// speedup vs baseline: 2.4850x; 1.0088x over previous
#include <cuda_runtime.h>
#include <cuda_bf16.h>
#include <stdint.h>

// ---------------- problem constants ----------------
#define NB   64
#define CH   256
#define HH   28
#define WW   28
#define HPX  900              // 30*30 padded pixels per image
#define NPIX (NB*HPX)         // 57600
#define NPIX_PAD 57728        // slack for tap offsets on garbage rows
#define MT   128              // pixels (M) per CTA
#define NMT  (NPIX/MT)        // 450
#define NSTAGE 36             // 9 taps * 4 ic-chunks (64 ic each)
#define NBUF 3
#define A_BYTES 16384         // 128 rows * 128B
#define B_BYTES 16384         // 128 rows * 128B
#define STAGE_BYTES (A_BYTES + B_BYTES)        // 32768
#define SMEM_TOTAL (NBUF*STAGE_BYTES)          // 98304 -> 2 CTAs/SM

// ---------------- device scratch (no cudaMalloc allowed) ----------------
__device__ __align__(16) __nv_bfloat16 g_axs [(size_t)NPIX_PAD*CH];  // x - z_x, pad 0
__device__ __align__(16) __nv_bfloat16 g_amid[(size_t)NPIX_PAD*CH];  // mid - z_c1, pad 0
__device__ __align__(16) __nv_bfloat16 g_wb1[9*CH*CH];               // [tap][oc][ic]
__device__ __align__(16) __nv_bfloat16 g_wb2[9*CH*CH];

// ---------------- PTX helpers ----------------
__device__ __forceinline__ uint32_t smem_u32(const void* p) {
    uint32_t a;
    asm("{ .reg .u64 t; cvta.to.shared.u64 t, %1; cvt.u32.u64 %0, t; }" : "=r"(a) : "l"(p));
    return a;
}
__device__ __forceinline__ void cp16(uint32_t sdst, const void* gsrc) {
    asm volatile("cp.async.cg.shared.global [%0], [%1], 16;" :: "r"(sdst), "l"(gsrc));
}
#define CP_COMMIT() asm volatile("cp.async.commit_group;" ::: "memory")
template <int N> __device__ __forceinline__ void cp_wait() {
    asm volatile("cp.async.wait_group %0;" :: "n"(N) : "memory");
}
__device__ __forceinline__ void ldm4(uint32_t* r, uint32_t addr) {
    asm volatile("ldmatrix.sync.aligned.m8n8.x4.shared.b16 {%0,%1,%2,%3}, [%4];"
        : "=r"(r[0]), "=r"(r[1]), "=r"(r[2]), "=r"(r[3]) : "r"(addr));
}
__device__ __forceinline__ void mma_bf16(float* d, const uint32_t* a, const uint32_t* b) {
    asm volatile("mma.sync.aligned.m16n8k16.row.col.f32.bf16.bf16.f32 "
        "{%0,%1,%2,%3},{%4,%5,%6,%7},{%8,%9},{%0,%1,%2,%3};"
        : "+f"(d[0]), "+f"(d[1]), "+f"(d[2]), "+f"(d[3])
        : "r"(a[0]), "r"(a[1]), "r"(a[2]), "r"(a[3]), "r"(b[0]), "r"(b[1]));
}

// ---------------- packing kernels ----------------
// zero ONLY padding ring + M-slack (interior fully overwritten later)
#define RING_SLOTS (64*116 + 128)       // 7552 pixel slots
__global__ void k_zero_halo() {
    int idx = blockIdx.x * blockDim.x + threadIdx.x;
    int total = RING_SLOTS * 32;
    if (idx >= 2 * total) return;
    int arr = idx >= total;
    int t = arr ? idx - total : idx;
    int chunk = t & 31;
    int slot  = t >> 5;
    size_t P;
    if (slot < 64 * 116) {
        int img = slot / 116, i = slot % 116;
        int q;
        if (i < 30)       q = i;
        else if (i < 60)  q = 870 + (i - 30);
        else if (i < 88)  q = (i - 60 + 1) * 30;
        else              q = (i - 88 + 1) * 30 + 29;
        P = (size_t)img * HPX + q;
    } else {
        P = (size_t)NPIX + (slot - 64 * 116);
    }
    int4 z = make_int4(0, 0, 0, 0);
    if (arr == 0) ((int4*)(g_axs  + P * 256))[chunk] = z;
    else          ((int4*)(g_amid + P * 256))[chunk] = z;
}

// x NCHW fp32 -> g_axs padded NHWC bf16 (x - z_x), smem transpose
__global__ void k_pack_x(const float* __restrict__ x, const float* __restrict__ pzx) {
    __shared__ __nv_bfloat16 s[28 * 258];
    int n  = blockIdx.x / 28;
    int oh = blockIdx.x % 28;
    float zx = *pzx;
    for (int i = threadIdx.x; i < 28 * 256; i += 256) {
        int c = i / 28, ow = i % 28;
        float g = x[(((size_t)n * CH + c) * HH + oh) * WW + ow];
        s[ow * 258 + c] = __float2bfloat16(__fsub_rn(g, zx));
    }
    __syncthreads();
    for (int i = threadIdx.x; i < 28 * 256; i += 256) {
        int ow = i >> 8, c = i & 255;
        g_axs[((size_t)n * HPX + (oh + 1) * 30 + ow + 1) * CH + c] = s[ow * 258 + c];
    }
}

// both weights OIHW fp32 -> [tap][oc][ic] bf16 in one kernel
__global__ void k_pack_w2(const float* __restrict__ w1, const float* __restrict__ w2) {
    int idx = blockIdx.x * blockDim.x + threadIdx.x;   // 2 * 9*256*256
    int which = idx >= 9*256*256;
    int j = which ? idx - 9*256*256 : idx;
    int ic  = j & 255;
    int oc  = (j >> 8) & 255;
    int tap = j >> 16;
    const float* w = which ? w2 : w1;
    __nv_bfloat16 v = __float2bfloat16(w[((size_t)oc * CH + ic) * 9 + tap]);
    if (which == 0) g_wb1[j] = v; else g_wb2[j] = v;
}

// ---------------- bf16 HMMA implicit-GEMM conv ----------------
// CTA tile: 128 px x 128 oc; 4 warps, warp tile 64 px x 64 oc; 2 CTAs/SM.
// Fragment double-buffering: ldmatrix for group g+1 overlaps mma of group g.
// MODE 0: conv1, A = (x-z_x), writes g_amid = (mid - z_c1) bf16
// MODE 1: conv2, A = (mid - z_c1), fused residual qadd -> out fp32 NCHW
template <int MODE>
__global__ __launch_bounds__(128, 2) void k_conv(
    const float* __restrict__ ps_in,  const float* __restrict__ ps_w,
    const float* __restrict__ ps_out, const float* __restrict__ pz_out,
    const float* __restrict__ ps_x,   const float* __restrict__ ps_add,
    const float* __restrict__ pz_add,
    float* __restrict__ out)
{
    extern __shared__ char smem[];
    const uint32_t sb = smem_u32(smem);
    const __nv_bfloat16* act = (MODE == 0) ? g_axs : g_amid;
    const __nv_bfloat16* wq  = (MODE == 0) ? g_wb1 : g_wb2;

    const int tid  = threadIdx.x;
    const int lane = tid & 31;
    const int wid  = tid >> 5;
    const int wm   = wid & 1;           // 2 m-warps (64 px each)
    const int wn   = wid >> 1;          // 2 n-warps (64 oc each)
    const int P0   = blockIdx.x * MT;
    const int ocb  = blockIdx.y * 128;

    float acc[4][8][4];
#pragma unroll
    for (int mt = 0; mt < 4; mt++)
#pragma unroll
        for (int nt = 0; nt < 8; nt++)
#pragma unroll
            for (int j = 0; j < 4; j++) acc[mt][nt][j] = 0.f;

    // stage loader: tap = s/4, ic0 = (s%4)*64 ; A 1024 cp16 + B 1024 cp16, 128 thr
    auto load_stage = [&](int s) {
        int tap = s >> 2;
        int ic0 = (s & 3) * 64;
        int off = (tap / 3) * 30 + (tap % 3);
        uint32_t bufA = sb + (s % NBUF) * STAGE_BYTES;
        uint32_t bufB = bufA + A_BYTES;
        const char* ga = (const char*)act + (size_t)(P0 + off) * 512 + ic0 * 2;
        const char* gb = (const char*)wq + ((size_t)tap * 256 + ocb) * 512 + ic0 * 2;
#pragma unroll
        for (int i = 0; i < 8; i++) {
            int idx = tid + i * 128;            // 0..1023
            int row = idx >> 3, c16 = idx & 7;
            uint32_t sw = (uint32_t)(row * 128 + ((c16 ^ (row & 7)) << 4));
            cp16(bufA + sw, ga + (size_t)row * 512 + c16 * 16);
        }
#pragma unroll
        for (int i = 0; i < 8; i++) {
            int idx = tid + i * 128;
            int row = idx >> 3, c16 = idx & 7;
            uint32_t sw = (uint32_t)(row * 128 + ((c16 ^ (row & 7)) << 4));
            cp16(bufB + sw, gb + (size_t)row * 512 + c16 * 16);
        }
        CP_COMMIT();
    };

    load_stage(0); load_stage(1);

    // per-lane ldmatrix row/chunk selectors
    const int lrow = (lane & 7) + ((lane >> 3) & 1) * 8;
    const int lchk = lane >> 4;          // 0/1 -> 16B chunk within k16 group

    uint32_t afb[2][4][4];               // double-buffered fragments
    uint32_t bfb[2][8][2];

    // load fragments for k16 group g from (bufA, bufB) into slot d
    auto load_frags = [&](uint32_t bufA, uint32_t bufB, int g, int d) {
        const int c = (g << 1) | lchk;
#pragma unroll
        for (int mt = 0; mt < 4; mt++) {
            int r = wm * 64 + mt * 16 + lrow;
            ldm4(afb[d][mt], bufA + r * 128 + ((c ^ (r & 7)) << 4));
        }
#pragma unroll
        for (int nt2 = 0; nt2 < 4; nt2++) {
            int r = wn * 64 + nt2 * 16 + lrow;
            uint32_t rr[4];
            ldm4(rr, bufB + r * 128 + ((c ^ (r & 7)) << 4));
            bfb[d][nt2*2][0]   = rr[0]; bfb[d][nt2*2][1]   = rr[2];
            bfb[d][nt2*2+1][0] = rr[1]; bfb[d][nt2*2+1][1] = rr[3];
        }
    };

#pragma unroll 1
    for (int s = 0; s < NSTAGE; s++) {
        if (s == NSTAGE - 1) cp_wait<0>(); else cp_wait<1>();
        __syncthreads();

        uint32_t bufA = sb + (s % NBUF) * STAGE_BYTES;
        uint32_t bufB = bufA + A_BYTES;

        load_frags(bufA, bufB, 0, 0);          // prime group 0
        if (s + 2 < NSTAGE) load_stage(s + 2); // async loads overlap compute

#pragma unroll
        for (int g = 0; g < 4; g++) {
            if (g < 3) load_frags(bufA, bufB, g + 1, (g + 1) & 1);
            const int d = g & 1;
#pragma unroll
            for (int mt = 0; mt < 4; mt++)
#pragma unroll
                for (int nt = 0; nt < 8; nt++)
                    mma_bf16(acc[mt][nt], afb[d][mt], bfb[d][nt]);
        }
    }

    // ---------------- epilogue ----------------
    const float M  = __fdiv_rn(__fmul_rn(*ps_in, *ps_w), *ps_out);
    const float zo = *pz_out;
    const float lo = -zo, hi = 255.f - zo;     // clamp in shifted domain (zo integer)
    const int qrow = lane >> 2;
    const int cc   = (lane & 3) << 1;
    const int ocw  = ocb + wn * 64;

    float ra = 0.f, rb = 0.f, za = 0.f;
    if (MODE == 1) {
        ra = __fdiv_rn(*ps_x,   *ps_add);
        rb = __fdiv_rn(*ps_out, *ps_add);
        za = *pz_add;
    }

#pragma unroll
    for (int mt = 0; mt < 4; mt++) {
#pragma unroll
        for (int h = 0; h < 2; h++) {
            int r  = wm * 64 + mt * 16 + qrow + h * 8;
            int P  = P0 + r;
            int n  = P / HPX;
            int q  = P - n * HPX;
            int oh = q / 30, ow = q - oh * 30;
            if (oh >= 28 || ow >= 28) continue;

            if (MODE == 0) {
                size_t base = (size_t)(P + 31) * 256 + ocw + cc;
#pragma unroll
                for (int nt = 0; nt < 8; nt++) {
                    float t0 = fminf(fmaxf(rintf(__fmul_rn(M, acc[mt][nt][h*2])),   lo), hi);
                    float t1 = fminf(fmaxf(rintf(__fmul_rn(M, acc[mt][nt][h*2+1])), lo), hi);
                    __nv_bfloat162 u;
                    u.x = __float2bfloat16(t0);
                    u.y = __float2bfloat16(t1);
                    *(__nv_bfloat162*)(g_amid + base + nt * 8) = u;
                }
            } else {
                size_t xbase = (size_t)(P + 31) * 256 + ocw + cc;
#pragma unroll
                for (int nt = 0; nt < 8; nt++) {
                    float t0 = fminf(fmaxf(rintf(__fmul_rn(M, acc[mt][nt][h*2])),   lo), hi);
                    float t1 = fminf(fmaxf(rintf(__fmul_rn(M, acc[mt][nt][h*2+1])), lo), hi);
                    float xv0 = __bfloat162float(g_axs[xbase + nt * 8]);
                    float xv1 = __bfloat162float(g_axs[xbase + nt * 8 + 1]);
                    float y0 = __fadd_rn(__fmul_rn(ra, xv0), __fmul_rn(rb, t0));
                    float y1 = __fadd_rn(__fmul_rn(ra, xv1), __fmul_rn(rb, t1));
                    float o0 = fminf(fmaxf(rintf(y0) + za, 0.f), 255.f);
                    float o1 = fminf(fmaxf(rintf(y1) + za, 0.f), 255.f);
                    int oc = ocw + nt * 8 + cc;
                    out[((size_t)(n * CH + oc    ) * HH + oh) * WW + ow] = o0;
                    out[((size_t)(n * CH + oc + 1) * HH + oh) * WW + ow] = o1;
                }
            }
        }
    }
}

// ---------------- launch ----------------
extern "C" void kernel_launch(void* const* d_in, const int* in_sizes, int n_in,
                              void* d_out, int out_size) {
    const float* x    = (const float*)d_in[0];
    const float* w1   = (const float*)d_in[1];
    const float* w2   = (const float*)d_in[2];
    const float* s_x  = (const float*)d_in[3];
    const float* z_x  = (const float*)d_in[4];
    const float* s_w1 = (const float*)d_in[5];
    const float* s_c1 = (const float*)d_in[6];
    const float* z_c1 = (const float*)d_in[7];
    const float* s_w2 = (const float*)d_in[8];
    const float* s_c2 = (const float*)d_in[9];
    const float* z_c2 = (const float*)d_in[10];
    const float* s_ad = (const float*)d_in[11];
    const float* z_ad = (const float*)d_in[12];
    float* out = (float*)d_out;

    cudaFuncSetAttribute(k_conv<0>, cudaFuncAttributeMaxDynamicSharedMemorySize, SMEM_TOTAL);
    cudaFuncSetAttribute(k_conv<1>, cudaFuncAttributeMaxDynamicSharedMemorySize, SMEM_TOTAL);

    int zthreads = 2 * RING_SLOTS * 32;
    k_zero_halo<<<(zthreads + 255) / 256, 256>>>();
    k_pack_x<<<NB * HH, 256>>>(x, z_x);
    k_pack_w2<<<2 * 9 * 256, 256>>>(w1, w2);

    dim3 grid(NMT, 2);
    k_conv<0><<<grid, 128, SMEM_TOTAL>>>(s_x, s_w1, s_c1, z_c1,
                                         s_x, s_ad, z_ad, nullptr);
    k_conv<1><<<grid, 128, SMEM_TOTAL>>>(s_c1, s_w2, s_c2, z_c2,
                                         s_x, s_ad, z_ad, out);
}